// round 1
// baseline (speedup 1.0000x reference)
#include <cuda_runtime.h>

#define VOCAB 50257
#define NT 512
#define NFULL 98                 // j = 0..97 always in-bounds (97*512+511 = 50175 < VOCAB)
#define EPT 99
#define NVEC (VOCAB / 4)         // 12564 uint4, tail element index VOCAB-1
#define CAND_MAX 256
#define KEYS_BYTES ((VOCAB * 4 + 15) & ~15)   // 201040

struct Scratch {
    int      sredi[17];
    float    sredf[17];
    unsigned cbuf[CAND_MAX];
    int      ccnt;
    unsigned thrslot;
};

#define SMEM_TOTAL (KEYS_BYTES + (int)sizeof(Scratch))

// ---- order-preserving float <-> u32 key ----
__device__ __forceinline__ unsigned fkey(float f) {
    unsigned b = __float_as_uint(f);
    unsigned m = (unsigned)(((int)b) >> 31) | 0x80000000u;
    return b ^ m;
}
__device__ __forceinline__ float keyf(unsigned k) {
    unsigned m = (~(unsigned)(((int)k) >> 31)) | 0x80000000u;
    return __uint_as_float(k ^ m);
}

// ---- block reductions (512 threads = 16 warps) ----
__device__ __forceinline__ int blockSumI(int v, int* s) {
    #pragma unroll
    for (int o = 16; o; o >>= 1) v += __shfl_xor_sync(0xffffffffu, v, o);
    int wid = threadIdx.x >> 5, lane = threadIdx.x & 31;
    if (lane == 0) s[wid] = v;
    __syncthreads();
    if (wid == 0) {
        int x = (lane < (NT / 32)) ? s[lane] : 0;
        #pragma unroll
        for (int o = 8; o; o >>= 1) x += __shfl_xor_sync(0xffffffffu, x, o);
        if (lane == 0) s[16] = x;
    }
    __syncthreads();
    int r = s[16];
    __syncthreads();
    return r;
}

__device__ __forceinline__ float blockMaxF(float v, float* s) {
    #pragma unroll
    for (int o = 16; o; o >>= 1) v = fmaxf(v, __shfl_xor_sync(0xffffffffu, v, o));
    int wid = threadIdx.x >> 5, lane = threadIdx.x & 31;
    if (lane == 0) s[wid] = v;
    __syncthreads();
    if (wid == 0) {
        float x = (lane < (NT / 32)) ? s[lane] : -3.402823466e38f;
        #pragma unroll
        for (int o = 8; o; o >>= 1) x = fmaxf(x, __shfl_xor_sync(0xffffffffu, x, o));
        if (lane == 0) s[16] = x;
    }
    __syncthreads();
    float r = s[16];
    __syncthreads();
    return r;
}

__device__ __forceinline__ float blockSumF(float v, float* s) {
    #pragma unroll
    for (int o = 16; o; o >>= 1) v += __shfl_xor_sync(0xffffffffu, v, o);
    int wid = threadIdx.x >> 5, lane = threadIdx.x & 31;
    if (lane == 0) s[wid] = v;
    __syncthreads();
    if (wid == 0) {
        float x = (lane < (NT / 32)) ? s[lane] : 0.0f;
        #pragma unroll
        for (int o = 8; o; o >>= 1) x += __shfl_xor_sync(0xffffffffu, x, o);
        if (lane == 0) s[16] = x;
    }
    __syncthreads();
    float r = s[16];
    __syncthreads();
    return r;
}

// noise = -log(-log(u + EPS) + EPS), with an exact log1p polynomial for u near 1
// (u -> 1 is exactly the top-k-defining region; MUFU LG2's absolute error there
//  would otherwise amplify to ~1e-2 in the noise).
__device__ __forceinline__ float gumbel_noise(float uu) {
    float vlog = -__logf(uu + 1e-10f);
    float d = uu - 1.0f;                         // exact (Sterbenz) for uu in [0.5, 2)
    float p = __fmaf_rn(-0.25f, d, 0.33333333f); // log1p(d) = d*(1 - d/2 + d^2/3 - d^3/4)
    p = __fmaf_rn(p, d, -0.5f);
    p = __fmaf_rn(p, d, 1.0f);
    float vpoly = -(d * p);
    float v = (uu > 0.99f) ? vpoly : vlog;
    return -__logf(v + 1e-10f);
}

__global__ void __launch_bounds__(NT, 1)
gumbel_sampler_kernel(const float* __restrict__ logits,
                      const float* __restrict__ uin,
                      const int* __restrict__ kp,
                      float* __restrict__ out)
{
    extern __shared__ unsigned char smem_raw[];
    unsigned* keys = (unsigned*)smem_raw;
    Scratch*  sc   = (Scratch*)(smem_raw + KEYS_BYTES);

    const int row = blockIdx.x;
    const int tid = threadIdx.x;
    const float* __restrict__ lrow = logits + (size_t)row * VOCAB;
    const float* __restrict__ urow = uin    + (size_t)row * VOCAB;
    float* __restrict__ orow = out + (size_t)row * VOCAB;
    const int k = *kp;

    float lreg[EPT];

    // ---------------- P1: load + gumbel + keys into smem ----------------
    #pragma unroll
    for (int j = 0; j < NFULL; ++j) {
        int idx = tid + j * NT;
        float l = lrow[idx];
        float g = l + gumbel_noise(urow[idx]);
        lreg[j] = l;
        keys[idx] = fkey(g);
    }
    {
        int idx = tid + NFULL * NT;
        if (idx < VOCAB) {
            float l = lrow[idx];
            float g = l + gumbel_noise(urow[idx]);
            lreg[NFULL] = l;
            keys[idx] = fkey(g);
        }
    }
    __syncthreads();

    // ---------------- P2: exact k-th largest via key bisection ----------------
    unsigned lo = 0u, hi = 0xFFFFFFFFu;
    int c_lo = VOCAB, c_hi = 0;
    const uint4* kv = (const uint4*)keys;

    while ((hi - lo) > 1u && (c_lo - c_hi) > CAND_MAX) {
        unsigned mid = lo + ((hi - lo) >> 1);
        int cnt = 0;
        #pragma unroll 4
        for (int i = tid; i < NVEC; i += NT) {
            uint4 x = kv[i];
            cnt += (x.x >= mid) + (x.y >= mid) + (x.z >= mid) + (x.w >= mid);
        }
        if (tid == 0) cnt += (keys[VOCAB - 1] >= mid);
        cnt = blockSumI(cnt, sc->sredi);
        if (cnt >= k) { lo = mid; c_lo = cnt; }
        else          { hi = mid; c_hi = cnt; }
    }

    unsigned thrKey;
    if ((hi - lo) <= 1u) {
        thrKey = lo;   // count(>=lo) >= k > count(>=lo+1)  =>  lo is the k-th largest key
    } else {
        // gather the (<=256) candidates in [lo, hi)
        if (tid == 0) sc->ccnt = 0;
        __syncthreads();
        for (int i = tid; i < NVEC; i += NT) {
            uint4 x = kv[i];
            if (x.x >= lo && x.x < hi) { int p = atomicAdd(&sc->ccnt, 1); if (p < CAND_MAX) sc->cbuf[p] = x.x; }
            if (x.y >= lo && x.y < hi) { int p = atomicAdd(&sc->ccnt, 1); if (p < CAND_MAX) sc->cbuf[p] = x.y; }
            if (x.z >= lo && x.z < hi) { int p = atomicAdd(&sc->ccnt, 1); if (p < CAND_MAX) sc->cbuf[p] = x.z; }
            if (x.w >= lo && x.w < hi) { int p = atomicAdd(&sc->ccnt, 1); if (p < CAND_MAX) sc->cbuf[p] = x.w; }
        }
        if (tid == 0) {
            unsigned x = keys[VOCAB - 1];
            if (x >= lo && x < hi) { int p = atomicAdd(&sc->ccnt, 1); if (p < CAND_MAX) sc->cbuf[p] = x; }
        }
        __syncthreads();
        int m = sc->ccnt;
        if (m > CAND_MAX) m = CAND_MAX;
        int need = k - c_hi;   // rank (1-indexed, descending) within candidates
        if (tid < m) {
            unsigned kt = sc->cbuf[tid];
            int gt = 0, ge = 0;
            for (int j = 0; j < m; ++j) {
                unsigned kj = sc->cbuf[j];
                gt += (kj > kt);
                ge += (kj >= kt);
            }
            if (gt < need && need <= ge) sc->thrslot = kt;
        }
        __syncthreads();
        thrKey = sc->thrslot;
    }

    const float thr = keyf(thrKey);

    // ---------------- P3: mask + softmax ----------------
    float* mvals = (float*)keys;   // reuse smem: keys -> masked logits -> exp values
    float lmax = -3.402823466e38f;

    #pragma unroll
    for (int j = 0; j < NFULL; ++j) {
        int idx = tid + j * NT;
        float g = keyf(keys[idx]);
        float s = __fdividef(1.0f, 1.0f + __expf(thr - g));
        float mk = lreg[j] * s;
        mvals[idx] = mk;
        lmax = fmaxf(lmax, mk);
    }
    {
        int idx = tid + NFULL * NT;
        if (idx < VOCAB) {
            float g = keyf(keys[idx]);
            float s = __fdividef(1.0f, 1.0f + __expf(thr - g));
            float mk = lreg[NFULL] * s;
            mvals[idx] = mk;
            lmax = fmaxf(lmax, mk);
        }
    }
    float M = blockMaxF(lmax, sc->sredf);

    float lsum = 0.0f;
    for (int idx = tid; idx < VOCAB; idx += NT) {
        float e = __expf(mvals[idx] - M);
        lsum += e;
        mvals[idx] = e;
    }
    float S = blockSumF(lsum, sc->sredf);
    float inv = __fdividef(1.0f, S);

    for (int idx = tid; idx < VOCAB; idx += NT) {
        orow[idx] = mvals[idx] * inv;
    }
}

extern "C" void kernel_launch(void* const* d_in, const int* in_sizes, int n_in,
                              void* d_out, int out_size)
{
    const float* logits = (const float*)d_in[0];
    const float* u      = (const float*)d_in[1];
    const int*   kp     = (const int*)d_in[2];
    float* out = (float*)d_out;

    int B = out_size / VOCAB;

    cudaFuncSetAttribute(gumbel_sampler_kernel,
                         cudaFuncAttributeMaxDynamicSharedMemorySize, SMEM_TOTAL);
    gumbel_sampler_kernel<<<B, NT, SMEM_TOTAL>>>(logits, u, kp, out);
}